// round 1
// baseline (speedup 1.0000x reference)
#include <cuda_runtime.h>
#include <math.h>

#define NN  8
#define CC  128
#define HH  96
#define WW  96
#define HWp (HH*WW)          // 9216
#define CHW (CC*HWp)         // 1179648
#define GG  8
#define GCg 16
#define OMD 216

// ---------------- scratch (device globals; no allocation) ----------------
__device__ float g_x1 [NN*CHW];        // dwconv output, NCHW
__device__ float g_act[NN*CHW];        // norm+gelu, NHWC  (GEMM A)
__device__ float g_xT [NN*CHW];        // raw input transposed to NHWC
__device__ float g_om [(size_t)NN*HWp*OMD]; // linear head output
__device__ float g_sum[NN];
__device__ float g_sq [NN];
__device__ float g_mean[NN];
__device__ float g_rsig[NN];

// ---------------- kernel 0: zero stats (replay-safe) ----------------
__global__ void zero_stats_k() {
    int t = threadIdx.x;
    if (t < NN) { g_sum[t] = 0.f; g_sq[t] = 0.f; }
}

// ---------------- kernel 1: depthwise 3x3 conv + bias + partial stats ----------------
__global__ void dwconv_k(const float* __restrict__ x,
                         const float* __restrict__ dw_w,
                         const float* __restrict__ dw_b) {
    int idx = blockIdx.x * 256 + threadIdx.x;  // over NN*CHW; blocks never cross n
    int wpos = idx % WW;
    int t    = idx / WW;
    int hpos = t % HH;  t /= HH;
    int c    = t % CC;
    int n    = t / CC;

    const float* xp = x + ((size_t)n*CC + c)*HWp;
    const float* wp = dw_w + c*9;
    float acc = dw_b[c];
    #pragma unroll
    for (int ky = 0; ky < 3; ky++) {
        int yy = hpos + ky - 1;
        if (yy < 0 || yy >= HH) continue;
        #pragma unroll
        for (int kx = 0; kx < 3; kx++) {
            int xx = wpos + kx - 1;
            if (xx < 0 || xx >= WW) continue;
            acc += xp[yy*WW + xx] * wp[ky*3 + kx];
        }
    }
    g_x1[idx] = acc;

    // block reduction for per-sample mean/var
    __shared__ float ssum[256];
    __shared__ float ssq [256];
    int tid = threadIdx.x;
    ssum[tid] = acc;
    ssq [tid] = acc * acc;
    __syncthreads();
    for (int s = 128; s > 0; s >>= 1) {
        if (tid < s) { ssum[tid] += ssum[tid+s]; ssq[tid] += ssq[tid+s]; }
        __syncthreads();
    }
    if (tid == 0) {
        atomicAdd(&g_sum[n], ssum[0]);
        atomicAdd(&g_sq [n], ssq [0]);
    }
}

// ---------------- kernel 2: finalize mean / rsig ----------------
__global__ void finalize_k() {
    int t = threadIdx.x;
    if (t < NN) {
        float inv = 1.f / (float)CHW;
        float mu  = g_sum[t] * inv;
        float var = g_sq[t] * inv - mu*mu;
        g_mean[t] = mu;
        g_rsig[t] = rsqrtf(var + 1e-5f);
    }
}

// ---------------- kernel 3: normalize + affine + GELU + transpose NCHW->NHWC ----------------
__global__ void normgelu_t_k(const float* __restrict__ gn_w,
                             const float* __restrict__ gn_b) {
    __shared__ float tile[32][33];
    int n  = blockIdx.z;
    int c0 = blockIdx.y * 32;
    int p0 = blockIdx.x * 32;
    int tx = threadIdx.x, ty = threadIdx.y;  // 32 x 8

    const float* src = g_x1 + (size_t)n*CHW;
    #pragma unroll
    for (int i = ty; i < 32; i += 8)
        tile[i][tx] = src[(size_t)(c0 + i)*HWp + p0 + tx];
    __syncthreads();

    float mu = g_mean[n], rs = g_rsig[n];
    int c = c0 + tx;
    float w = gn_w[c], b = gn_b[c];
    float* dst = g_act + (size_t)n*CHW;
    #pragma unroll
    for (int i = ty; i < 32; i += 8) {
        float y = (tile[tx][i] - mu) * rs * w + b;
        float g = 0.5f * y * (1.f + erff(y * 0.70710678118654752f));
        dst[(size_t)(p0 + i)*CC + c] = g;
    }
}

// ---------------- kernel 4: plain transpose NCHW->NHWC of raw input ----------------
__global__ void transpose_x_k(const float* __restrict__ x) {
    __shared__ float tile[32][33];
    int n  = blockIdx.z;
    int c0 = blockIdx.y * 32;
    int p0 = blockIdx.x * 32;
    int tx = threadIdx.x, ty = threadIdx.y;

    const float* src = x + (size_t)n*CHW;
    #pragma unroll
    for (int i = ty; i < 32; i += 8)
        tile[i][tx] = src[(size_t)(c0 + i)*HWp + p0 + tx];
    __syncthreads();
    float* dst = g_xT + (size_t)n*CHW;
    #pragma unroll
    for (int i = ty; i < 32; i += 8)
        dst[(size_t)(p0 + i)*CC + c0 + tx] = tile[tx][i];
}

// ---------------- kernel 5: SGEMM  om = act[M,128] @ om_w^T[128,216] + om_b ----------------
// BM=64, BN=64, BK=16, 256 threads, 4x4 microtile
__global__ void gemm_k(const float* __restrict__ Bw,   // om_w [216,128] row-major
                       const float* __restrict__ bias) {
    __shared__ float As[16][65];
    __shared__ float Bs[16][65];
    int row0 = blockIdx.x * 64;
    int col0 = blockIdx.y * 64;
    int tid  = threadIdx.x;
    int tx = tid & 15, ty = tid >> 4;

    float acc[4][4] = {};
    for (int k0 = 0; k0 < 128; k0 += 16) {
        #pragma unroll
        for (int t = tid; t < 1024; t += 256) {
            int r = t >> 4, kk = t & 15;
            As[kk][r] = g_act[(size_t)(row0 + r)*CC + k0 + kk];
        }
        #pragma unroll
        for (int t = tid; t < 1024; t += 256) {
            int o = t >> 4, kk = t & 15;
            int col = col0 + o;
            Bs[kk][o] = (col < OMD) ? Bw[(size_t)col*CC + k0 + kk] : 0.f;
        }
        __syncthreads();
        #pragma unroll
        for (int kk = 0; kk < 16; kk++) {
            float a[4], b[4];
            #pragma unroll
            for (int i = 0; i < 4; i++) a[i] = As[kk][ty*4 + i];
            #pragma unroll
            for (int j = 0; j < 4; j++) b[j] = Bs[kk][tx*4 + j];
            #pragma unroll
            for (int i = 0; i < 4; i++)
                #pragma unroll
                for (int j = 0; j < 4; j++)
                    acc[i][j] += a[i] * b[j];
        }
        __syncthreads();
    }
    #pragma unroll
    for (int i = 0; i < 4; i++) {
        int row = row0 + ty*4 + i;
        #pragma unroll
        for (int j = 0; j < 4; j++) {
            int col = col0 + tx*4 + j;
            if (col < OMD)
                g_om[(size_t)row*OMD + col] = acc[i][j] + bias[col];
        }
    }
}

// ---------------- kernel 6: deformable bilinear sampling ----------------
// block: 256 threads = 16 channels (tx) x 16 w-positions (u); unit = (n,g,h,w)
__global__ void sample_k(float* __restrict__ out) {
    int b  = blockIdx.x;
    int wt = b % (WW/16); b /= (WW/16);
    int h  = b % HH;      b /= HH;
    int g  = b % GG;
    int n  = b / GG;
    int w0 = wt * 16;
    int tid = threadIdx.x;

    __shared__ float oms[16][28];
    for (int t = tid; t < 16*27; t += 256) {
        int u = t / 27, j = t % 27;
        oms[u][j] = g_om[((size_t)(n*HWp + h*WW + w0 + u))*OMD + g*27 + j];
    }
    __syncthreads();

    int c = tid & 15;
    int u = tid >> 4;
    int wpix = w0 + u;
    const float* xb = g_xT + (size_t)n*CHW + g*GCg + c;

    float acc = 0.f;
    #pragma unroll
    for (int k = 0; k < 9; k++) {
        int ky = k / 3, kx = k % 3;
        float locy = (float)(h    + ky - 1) + oms[u][2*k + 1];
        float locx = (float)(wpix + kx - 1) + oms[u][2*k];
        float m    = oms[u][18 + k];
        float fy0 = floorf(locy), fx0 = floorf(locx);
        float ly = locy - fy0, lx = locx - fx0;
        int y0 = (int)fy0, x0 = (int)fx0;
        int y1 = y0 + 1,   x1 = x0 + 1;
        bool yo0 = (y0 >= 0) & (y0 < HH), yo1 = (y1 >= 0) & (y1 < HH);
        bool xo0 = (x0 >= 0) & (x0 < WW), xo1 = (x1 >= 0) & (x1 < WW);
        float v00 = (yo0 & xo0) ? xb[(size_t)(y0*WW + x0)*CC] : 0.f;
        float v01 = (yo0 & xo1) ? xb[(size_t)(y0*WW + x1)*CC] : 0.f;
        float v10 = (yo1 & xo0) ? xb[(size_t)(y1*WW + x0)*CC] : 0.f;
        float v11 = (yo1 & xo1) ? xb[(size_t)(y1*WW + x1)*CC] : 0.f;
        acc += m * (v00*(1.f-ly)*(1.f-lx) + v01*(1.f-ly)*lx
                  + v10*ly*(1.f-lx)       + v11*ly*lx);
    }

    __shared__ float tout[16][17];
    tout[c][u] = acc;
    __syncthreads();
    // remap so consecutive lanes write consecutive w
    int c2 = tid >> 4, w2 = tid & 15;
    out[((size_t)(n*CC + g*GCg + c2))*HWp + h*WW + w0 + w2] = tout[c2][w2];
}

// ---------------- launch ----------------
extern "C" void kernel_launch(void* const* d_in, const int* in_sizes, int n_in,
                              void* d_out, int out_size) {
    const float* x    = (const float*)d_in[0];
    const float* dw_w = (const float*)d_in[1];
    const float* dw_b = (const float*)d_in[2];
    const float* gn_w = (const float*)d_in[3];
    const float* gn_b = (const float*)d_in[4];
    const float* om_w = (const float*)d_in[5];
    const float* om_b = (const float*)d_in[6];
    float* out = (float*)d_out;

    zero_stats_k<<<1, 32>>>();
    dwconv_k<<<NN*CHW/256, 256>>>(x, dw_w, dw_b);
    finalize_k<<<1, 32>>>();

    dim3 tb(32, 8);
    dim3 tg(HWp/32, CC/32, NN);
    normgelu_t_k<<<tg, tb>>>(gn_w, gn_b);
    transpose_x_k<<<tg, tb>>>(x);

    dim3 gg((NN*HWp)/64, (OMD + 63)/64);
    gemm_k<<<gg, 256>>>(om_w, om_b);

    sample_k<<<NN*GG*HH*(WW/16), 256>>>(out);
}

// round 5
// speedup vs baseline: 1.2143x; 1.2143x over previous
#include <cuda_runtime.h>
#include <math.h>

#define NN  8
#define CC  128
#define HH  96
#define WW  96
#define HWp (HH*WW)          // 9216
#define CHW (CC*HWp)         // 1179648
#define GG  8
#define GCg 16
#define OMD 216

// ---------------- scratch (device globals; no allocation) ----------------
__device__ float g_x1 [NN*CHW];        // dwconv output, NCHW
__device__ float g_act[NN*CHW];        // norm+gelu, NHWC  (GEMM A)
__device__ float g_xT [NN*CHW];        // raw input transposed to NHWC
__device__ float g_om [(size_t)NN*HWp*OMD]; // linear head output
__device__ float g_sum[NN];
__device__ float g_sq [NN];
__device__ float g_mean[NN];
__device__ float g_rsig[NN];

// ---------------- kernel 0: zero stats (replay-safe) ----------------
__global__ void zero_stats_k() {
    int t = threadIdx.x;
    if (t < NN) { g_sum[t] = 0.f; g_sq[t] = 0.f; }
}

// ---------------- kernel 1: depthwise 3x3 conv + bias + partial stats ----------------
// Each thread computes 4 consecutive w outputs (float4 loads/stores).
__global__ void dwconv_k(const float* __restrict__ x,
                         const float* __restrict__ dw_w,
                         const float* __restrict__ dw_b) {
    int idx = blockIdx.x * 256 + threadIdx.x;   // over NN*CC*HH*(WW/4); blocks never cross n
    int wq = idx % (WW/4);
    int t  = idx / (WW/4);
    int h  = t % HH;  t /= HH;
    int c  = t % CC;
    int n  = t / CC;
    int w0 = wq * 4;

    const float* xp = x + ((size_t)n*CC + c)*HWp;
    const float* wp = dw_w + c*9;
    float bb = dw_b[c];
    float a0 = bb, a1 = bb, a2 = bb, a3 = bb;

    #pragma unroll
    for (int ky = 0; ky < 3; ky++) {
        int yy = h + ky - 1;
        if (yy < 0 || yy >= HH) continue;
        const float* row = xp + yy*WW + w0;
        float4 v  = *(const float4*)row;
        float vm  = (w0 > 0)       ? row[-1] : 0.f;
        float vp  = (w0 + 4 < WW)  ? row[4]  : 0.f;
        float k0 = wp[ky*3+0], k1 = wp[ky*3+1], k2 = wp[ky*3+2];
        a0 += k0*vm  + k1*v.x + k2*v.y;
        a1 += k0*v.x + k1*v.y + k2*v.z;
        a2 += k0*v.y + k1*v.z + k2*v.w;
        a3 += k0*v.z + k1*v.w + k2*vp;
    }
    *(float4*)&g_x1[((size_t)n*CC + c)*HWp + h*WW + w0] = make_float4(a0,a1,a2,a3);

    // block reduction for per-sample mean/var
    __shared__ float ssum[256];
    __shared__ float ssq [256];
    int tid = threadIdx.x;
    ssum[tid] = a0 + a1 + a2 + a3;
    ssq [tid] = a0*a0 + a1*a1 + a2*a2 + a3*a3;
    __syncthreads();
    for (int s = 128; s > 0; s >>= 1) {
        if (tid < s) { ssum[tid] += ssum[tid+s]; ssq[tid] += ssq[tid+s]; }
        __syncthreads();
    }
    if (tid == 0) {
        atomicAdd(&g_sum[n], ssum[0]);
        atomicAdd(&g_sq [n], ssq [0]);
    }
}

// ---------------- kernel 2: finalize mean / rsig ----------------
__global__ void finalize_k() {
    int t = threadIdx.x;
    if (t < NN) {
        float inv = 1.f / (float)CHW;
        float mu  = g_sum[t] * inv;
        float var = g_sq[t] * inv - mu*mu;
        g_mean[t] = mu;
        g_rsig[t] = rsqrtf(var + 1e-5f);
    }
}

// ---------------- kernel 3: fused (norm+GELU transpose) + (x transpose) ----------------
// One block handles the same 32x32 (c,p) tile of BOTH g_x1 (->g_act) and x (->g_xT).
__global__ void fused_transpose_k(const float* __restrict__ x,
                                  const float* __restrict__ gn_w,
                                  const float* __restrict__ gn_b) {
    __shared__ float tA[32][33];   // g_x1 tile
    __shared__ float tB[32][33];   // x tile
    int n  = blockIdx.z;
    int c0 = blockIdx.y * 32;
    int p0 = blockIdx.x * 32;
    int tx = threadIdx.x, ty = threadIdx.y;  // 32 x 8

    const float* srcA = g_x1 + (size_t)n*CHW;
    const float* srcB = x    + (size_t)n*CHW;
    #pragma unroll
    for (int i = ty; i < 32; i += 8) {
        size_t off = (size_t)(c0 + i)*HWp + p0 + tx;
        tA[i][tx] = srcA[off];
        tB[i][tx] = srcB[off];
    }
    __syncthreads();

    float mu = g_mean[n], rs = g_rsig[n];
    int c = c0 + tx;
    float w = gn_w[c], b = gn_b[c];
    float* dstA = g_act + (size_t)n*CHW;
    float* dstB = g_xT  + (size_t)n*CHW;
    #pragma unroll
    for (int i = ty; i < 32; i += 8) {
        float y = (tA[tx][i] - mu) * rs * w + b;
        float g = 0.5f * y * (1.f + erff(y * 0.70710678118654752f));
        size_t off = (size_t)(p0 + i)*CC + c;
        dstA[off] = g;
        dstB[off] = tB[tx][i];
    }
}

// ---------------- kernel 5: SGEMM  om = act[M,128] @ om_w^T[128,216] + om_b ----------------
// BM=128, BN=64, BK=16, 128 threads, 8x8 microtile, float4 everywhere,
// register-prefetch double buffering.
#define BM 128
#define BN 64
#define BK 16

__global__ void __launch_bounds__(128) gemm_k(const float* __restrict__ Bw,   // om_w [216,128]
                                              const float* __restrict__ bias) {
    __shared__ float As[BK][BM + 4];   // 16 x 132
    __shared__ float Bs[BK][BN + 8];   // 16 x 72

    const int tid  = threadIdx.x;
    const int row0 = blockIdx.x * BM;
    const int col0 = blockIdx.y * BN;
    const int mt   = tid >> 3;   // 0..15
    const int nt   = tid & 7;    // 0..7

    float4 pa[4], pb[2];

    #pragma unroll
    for (int i = 0; i < 4; i++) {
        int idx = tid + i*128;
        int r = idx >> 2, kq = idx & 3;
        pa[i] = *(const float4*)&g_act[(size_t)(row0 + r)*CC + kq*4];
    }
    #pragma unroll
    for (int i = 0; i < 2; i++) {
        int idx = tid + i*128;
        int nn = idx >> 2, kq = idx & 3;
        int col = col0 + nn;
        pb[i] = (col < OMD) ? *(const float4*)&Bw[(size_t)col*CC + kq*4]
                            : make_float4(0.f,0.f,0.f,0.f);
    }

    #pragma unroll
    for (int i = 0; i < 4; i++) {
        int idx = tid + i*128;
        int r = idx >> 2, kq = idx & 3;
        As[kq*4+0][r] = pa[i].x; As[kq*4+1][r] = pa[i].y;
        As[kq*4+2][r] = pa[i].z; As[kq*4+3][r] = pa[i].w;
    }
    #pragma unroll
    for (int i = 0; i < 2; i++) {
        int idx = tid + i*128;
        int nn = idx >> 2, kq = idx & 3;
        Bs[kq*4+0][nn] = pb[i].x; Bs[kq*4+1][nn] = pb[i].y;
        Bs[kq*4+2][nn] = pb[i].z; Bs[kq*4+3][nn] = pb[i].w;
    }
    __syncthreads();

    float acc[8][8] = {};

    #pragma unroll
    for (int it = 0; it < CC/BK; it++) {
        if (it < CC/BK - 1) {
            int k0 = (it + 1) * BK;
            #pragma unroll
            for (int i = 0; i < 4; i++) {
                int idx = tid + i*128;
                int r = idx >> 2, kq = idx & 3;
                pa[i] = *(const float4*)&g_act[(size_t)(row0 + r)*CC + k0 + kq*4];
            }
            #pragma unroll
            for (int i = 0; i < 2; i++) {
                int idx = tid + i*128;
                int nn = idx >> 2, kq = idx & 3;
                int col = col0 + nn;
                pb[i] = (col < OMD) ? *(const float4*)&Bw[(size_t)col*CC + k0 + kq*4]
                                    : make_float4(0.f,0.f,0.f,0.f);
            }
        }

        #pragma unroll
        for (int kk = 0; kk < BK; kk++) {
            float4 a0 = *(const float4*)&As[kk][mt*8];
            float4 a1 = *(const float4*)&As[kk][mt*8 + 4];
            float4 b0 = *(const float4*)&Bs[kk][nt*8];
            float4 b1 = *(const float4*)&Bs[kk][nt*8 + 4];
            float a[8] = {a0.x,a0.y,a0.z,a0.w,a1.x,a1.y,a1.z,a1.w};
            float b[8] = {b0.x,b0.y,b0.z,b0.w,b1.x,b1.y,b1.z,b1.w};
            #pragma unroll
            for (int i = 0; i < 8; i++)
                #pragma unroll
                for (int j = 0; j < 8; j++)
                    acc[i][j] += a[i] * b[j];
        }
        __syncthreads();

        if (it < CC/BK - 1) {
            #pragma unroll
            for (int i = 0; i < 4; i++) {
                int idx = tid + i*128;
                int r = idx >> 2, kq = idx & 3;
                As[kq*4+0][r] = pa[i].x; As[kq*4+1][r] = pa[i].y;
                As[kq*4+2][r] = pa[i].z; As[kq*4+3][r] = pa[i].w;
            }
            #pragma unroll
            for (int i = 0; i < 2; i++) {
                int idx = tid + i*128;
                int nn = idx >> 2, kq = idx & 3;
                Bs[kq*4+0][nn] = pb[i].x; Bs[kq*4+1][nn] = pb[i].y;
                Bs[kq*4+2][nn] = pb[i].z; Bs[kq*4+3][nn] = pb[i].w;
            }
            __syncthreads();
        }
    }

    int colA = col0 + nt*8;
    if (colA < OMD) {
        float4 bz0 = *(const float4*)&bias[colA];
        float4 bz1 = *(const float4*)&bias[colA + 4];
        #pragma unroll
        for (int i = 0; i < 8; i++) {
            int row = row0 + mt*8 + i;
            float4 v0 = make_float4(acc[i][0]+bz0.x, acc[i][1]+bz0.y,
                                    acc[i][2]+bz0.z, acc[i][3]+bz0.w);
            float4 v1 = make_float4(acc[i][4]+bz1.x, acc[i][5]+bz1.y,
                                    acc[i][6]+bz1.z, acc[i][7]+bz1.w);
            *(float4*)&g_om[(size_t)row*OMD + colA]     = v0;
            *(float4*)&g_om[(size_t)row*OMD + colA + 4] = v1;
        }
    }
}

// ---------------- kernel 6: deformable bilinear sampling ----------------
// block: 256 threads = 16 channels x 16 w-positions; unit = (n,g,h,w)
__global__ void sample_k(float* __restrict__ out) {
    int b  = blockIdx.x;
    int wt = b % (WW/16); b /= (WW/16);
    int h  = b % HH;      b /= HH;
    int g  = b % GG;
    int n  = b / GG;
    int w0 = wt * 16;
    int tid = threadIdx.x;

    __shared__ float oms[16][28];
    for (int t = tid; t < 16*27; t += 256) {
        int u = t / 27, j = t % 27;
        oms[u][j] = g_om[((size_t)(n*HWp + h*WW + w0 + u))*OMD + g*27 + j];
    }
    __syncthreads();

    int c = tid & 15;
    int u = tid >> 4;
    int wpix = w0 + u;
    const float* xb = g_xT + (size_t)n*CHW + g*GCg + c;

    float acc = 0.f;
    #pragma unroll
    for (int k = 0; k < 9; k++) {
        int ky = k / 3, kx = k % 3;
        float locy = (float)(h    + ky - 1) + oms[u][2*k + 1];
        float locx = (float)(wpix + kx - 1) + oms[u][2*k];
        float m    = oms[u][18 + k];
        float fy0 = floorf(locy), fx0 = floorf(locx);
        float ly = locy - fy0, lx = locx - fx0;
        int y0 = (int)fy0, x0 = (int)fx0;
        int y1 = y0 + 1,   x1 = x0 + 1;
        bool yo0 = (y0 >= 0) & (y0 < HH), yo1 = (y1 >= 0) & (y1 < HH);
        bool xo0 = (x0 >= 0) & (x0 < WW), xo1 = (x1 >= 0) & (x1 < WW);
        float v00 = (yo0 & xo0) ? xb[(size_t)(y0*WW + x0)*CC] : 0.f;
        float v01 = (yo0 & xo1) ? xb[(size_t)(y0*WW + x1)*CC] : 0.f;
        float v10 = (yo1 & xo0) ? xb[(size_t)(y1*WW + x0)*CC] : 0.f;
        float v11 = (yo1 & xo1) ? xb[(size_t)(y1*WW + x1)*CC] : 0.f;
        acc += m * (v00*(1.f-ly)*(1.f-lx) + v01*(1.f-ly)*lx
                  + v10*ly*(1.f-lx)       + v11*ly*lx);
    }

    __shared__ float tout[16][17];
    tout[c][u] = acc;
    __syncthreads();
    int c2 = tid >> 4, w2 = tid & 15;
    out[((size_t)(n*CC + g*GCg + c2))*HWp + h*WW + w0 + w2] = tout[c2][w2];
}

// ---------------- launch ----------------
extern "C" void kernel_launch(void* const* d_in, const int* in_sizes, int n_in,
                              void* d_out, int out_size) {
    const float* x    = (const float*)d_in[0];
    const float* dw_w = (const float*)d_in[1];
    const float* dw_b = (const float*)d_in[2];
    const float* gn_w = (const float*)d_in[3];
    const float* gn_b = (const float*)d_in[4];
    const float* om_w = (const float*)d_in[5];
    const float* om_b = (const float*)d_in[6];
    float* out = (float*)d_out;

    zero_stats_k<<<1, 32>>>();
    dwconv_k<<<NN*CC*HH*(WW/4)/256, 256>>>(x, dw_w, dw_b);
    finalize_k<<<1, 32>>>();

    dim3 tb(32, 8);
    dim3 tg(HWp/32, CC/32, NN);
    fused_transpose_k<<<tg, tb>>>(x, gn_w, gn_b);

    dim3 gg((NN*HWp)/BM, (OMD + BN - 1)/BN);
    gemm_k<<<gg, 128>>>(om_w, om_b);

    sample_k<<<NN*GG*HH*(WW/16), 256>>>(out);
}

// round 6
// speedup vs baseline: 1.8389x; 1.5143x over previous
#include <cuda_runtime.h>
#include <math.h>

#define NN  8
#define CC  128
#define HH  96
#define WW  96
#define HWp (HH*WW)          // 9216
#define CHW (CC*HWp)         // 1179648
#define GG  8
#define GCg 16
#define OMD 216

// ---------------- scratch (device globals; no allocation) ----------------
__device__ float g_x1 [NN*CHW];        // dwconv output, NCHW
__device__ float g_act[NN*CHW];        // norm+gelu (tf32-rounded), NHWC (GEMM A)
__device__ float g_xT [NN*CHW];        // raw input transposed to NHWC
__device__ float g_om [(size_t)NN*HWp*OMD]; // linear head output
__device__ float g_sum[NN];
__device__ float g_sq [NN];
__device__ float g_mean[NN];
__device__ float g_rsig[NN];

__device__ __forceinline__ unsigned f2tf32(float x) {
    unsigned r;
    asm("cvt.rna.tf32.f32 %0, %1;" : "=r"(r) : "f"(x));
    return r;
}

// ---------------- kernel 0: zero stats (replay-safe) ----------------
__global__ void zero_stats_k() {
    int t = threadIdx.x;
    if (t < NN) { g_sum[t] = 0.f; g_sq[t] = 0.f; }
}

// ---------------- kernel 1: depthwise 3x3 conv + bias + partial stats ----------------
__global__ void dwconv_k(const float* __restrict__ x,
                         const float* __restrict__ dw_w,
                         const float* __restrict__ dw_b) {
    int idx = blockIdx.x * 256 + threadIdx.x;   // over NN*CC*HH*(WW/4)
    int wq = idx % (WW/4);
    int t  = idx / (WW/4);
    int h  = t % HH;  t /= HH;
    int c  = t % CC;
    int n  = t / CC;
    int w0 = wq * 4;

    const float* xp = x + ((size_t)n*CC + c)*HWp;
    const float* wp = dw_w + c*9;
    float bb = dw_b[c];
    float a0 = bb, a1 = bb, a2 = bb, a3 = bb;

    #pragma unroll
    for (int ky = 0; ky < 3; ky++) {
        int yy = h + ky - 1;
        if (yy < 0 || yy >= HH) continue;
        const float* row = xp + yy*WW + w0;
        float4 v  = *(const float4*)row;
        float vm  = (w0 > 0)       ? row[-1] : 0.f;
        float vp  = (w0 + 4 < WW)  ? row[4]  : 0.f;
        float k0 = wp[ky*3+0], k1 = wp[ky*3+1], k2 = wp[ky*3+2];
        a0 += k0*vm  + k1*v.x + k2*v.y;
        a1 += k0*v.x + k1*v.y + k2*v.z;
        a2 += k0*v.y + k1*v.z + k2*v.w;
        a3 += k0*v.z + k1*v.w + k2*vp;
    }
    *(float4*)&g_x1[((size_t)n*CC + c)*HWp + h*WW + w0] = make_float4(a0,a1,a2,a3);

    __shared__ float ssum[256];
    __shared__ float ssq [256];
    int tid = threadIdx.x;
    ssum[tid] = a0 + a1 + a2 + a3;
    ssq [tid] = a0*a0 + a1*a1 + a2*a2 + a3*a3;
    __syncthreads();
    for (int s = 128; s > 0; s >>= 1) {
        if (tid < s) { ssum[tid] += ssum[tid+s]; ssq[tid] += ssq[tid+s]; }
        __syncthreads();
    }
    if (tid == 0) {
        atomicAdd(&g_sum[n], ssum[0]);
        atomicAdd(&g_sq [n], ssq [0]);
    }
}

// ---------------- kernel 2: finalize mean / rsig ----------------
__global__ void finalize_k() {
    int t = threadIdx.x;
    if (t < NN) {
        float inv = 1.f / (float)CHW;
        float mu  = g_sum[t] * inv;
        float var = g_sq[t] * inv - mu*mu;
        g_mean[t] = mu;
        g_rsig[t] = rsqrtf(var + 1e-5f);
    }
}

// ---------------- kernel 3: fused (norm+GELU transpose, tf32-round) + (x transpose) ----------------
__global__ void fused_transpose_k(const float* __restrict__ x,
                                  const float* __restrict__ gn_w,
                                  const float* __restrict__ gn_b) {
    __shared__ float tA[32][33];
    __shared__ float tB[32][33];
    int n  = blockIdx.z;
    int c0 = blockIdx.y * 32;
    int p0 = blockIdx.x * 32;
    int tx = threadIdx.x, ty = threadIdx.y;  // 32 x 8

    const float* srcA = g_x1 + (size_t)n*CHW;
    const float* srcB = x    + (size_t)n*CHW;
    #pragma unroll
    for (int i = ty; i < 32; i += 8) {
        size_t off = (size_t)(c0 + i)*HWp + p0 + tx;
        tA[i][tx] = srcA[off];
        tB[i][tx] = srcB[off];
    }
    __syncthreads();

    float mu = g_mean[n], rs = g_rsig[n];
    int c = c0 + tx;
    float w = gn_w[c], b = gn_b[c];
    float* dstA = g_act + (size_t)n*CHW;
    float* dstB = g_xT  + (size_t)n*CHW;
    #pragma unroll
    for (int i = ty; i < 32; i += 8) {
        float y = (tA[tx][i] - mu) * rs * w + b;
        float g = 0.5f * y * (1.f + erff(y * 0.70710678118654752f));
        size_t off = (size_t)(p0 + i)*CC + c;
        dstA[off] = __uint_as_float(f2tf32(g));   // pre-rounded for mma
        dstB[off] = tB[tx][i];
    }
}

// ---------------- kernel 5: tf32 tensor-core GEMM  om = act @ om_w^T + om_b ----------------
// Block tile 64(M) x 72(N), full K=128 staged once. 128 threads = 4 warps,
// each warp: 16 rows x 72 cols = 9 mma n-tiles, 16 k-steps of m16n8k8.
#define GBM 64
#define GBN 72

__device__ __forceinline__ void mma_tf32(float* c,
                                         unsigned a0, unsigned a1, unsigned a2, unsigned a3,
                                         unsigned b0, unsigned b1) {
    asm volatile(
        "mma.sync.aligned.m16n8k8.row.col.f32.tf32.tf32.f32 "
        "{%0,%1,%2,%3}, {%4,%5,%6,%7}, {%8,%9}, {%0,%1,%2,%3};\n"
        : "+f"(c[0]), "+f"(c[1]), "+f"(c[2]), "+f"(c[3])
        : "r"(a0), "r"(a1), "r"(a2), "r"(a3), "r"(b0), "r"(b1));
}

__global__ void __launch_bounds__(128) gemm_tf32_k(const float* __restrict__ Bw,  // om_w [216,128]
                                                   const float* __restrict__ bias) {
    __shared__ float As[GBM][132];   // 64 x 128 (+4 pad)  -> fragment reads bank = lane
    __shared__ float Bs[GBN][132];   // 72 x 128 (+4 pad)

    const int tid  = threadIdx.x;
    const int wid  = tid >> 5;
    const int lane = tid & 31;
    const int row0 = blockIdx.x * GBM;
    const int col0 = blockIdx.y * GBN;

    // load A tile: 64 rows x 128 = 2048 float4
    #pragma unroll
    for (int i = 0; i < 16; i++) {
        int idx = tid + i*128;
        int r  = idx >> 5;          // 0..63
        int kq = idx & 31;          // 0..31 (float4 col)
        float4 v = *(const float4*)&g_act[(size_t)(row0 + r)*CC + kq*4];
        *(float4*)&As[r][kq*4] = v; // already tf32-rounded by producer
    }
    // load B tile: 72 rows x 128 = 2304 float4, cvt to tf32 at store
    #pragma unroll
    for (int i = 0; i < 18; i++) {
        int idx = tid + i*128;
        int r  = idx >> 5;          // 0..71
        int kq = idx & 31;
        float4 v = *(const float4*)&Bw[(size_t)(col0 + r)*CC + kq*4];
        Bs[r][kq*4+0] = __uint_as_float(f2tf32(v.x));
        Bs[r][kq*4+1] = __uint_as_float(f2tf32(v.y));
        Bs[r][kq*4+2] = __uint_as_float(f2tf32(v.z));
        Bs[r][kq*4+3] = __uint_as_float(f2tf32(v.w));
    }
    __syncthreads();

    const int mrow = wid*16 + (lane >> 2);   // fragment row (first half)
    const int kl   = lane & 3;

    float acc[9][4];
    #pragma unroll
    for (int t = 0; t < 9; t++)
        acc[t][0] = acc[t][1] = acc[t][2] = acc[t][3] = 0.f;

    #pragma unroll
    for (int k0 = 0; k0 < 128; k0 += 8) {
        unsigned a0 = __float_as_uint(As[mrow    ][k0 + kl]);
        unsigned a1 = __float_as_uint(As[mrow + 8][k0 + kl]);
        unsigned a2 = __float_as_uint(As[mrow    ][k0 + 4 + kl]);
        unsigned a3 = __float_as_uint(As[mrow + 8][k0 + 4 + kl]);
        #pragma unroll
        for (int nt = 0; nt < 9; nt++) {
            int bcol = nt*8 + (lane >> 2);
            unsigned b0 = __float_as_uint(Bs[bcol][k0 + kl]);
            unsigned b1 = __float_as_uint(Bs[bcol][k0 + 4 + kl]);
            mma_tf32(acc[nt], a0, a1, a2, a3, b0, b1);
        }
    }

    // epilogue: c0/c1 at (row, 2c),(row,2c+1); c2/c3 at row+8. float2 stores + bias.
    const int rA = row0 + wid*16 + (lane >> 2);
    const int cBase = col0 + 2*(lane & 3);
    #pragma unroll
    for (int nt = 0; nt < 9; nt++) {
        int col = cBase + nt*8;
        float bx = bias[col], by = bias[col+1];
        *(float2*)&g_om[(size_t)rA*OMD + col]       = make_float2(acc[nt][0]+bx, acc[nt][1]+by);
        *(float2*)&g_om[(size_t)(rA+8)*OMD + col]   = make_float2(acc[nt][2]+bx, acc[nt][3]+by);
    }
}

// ---------------- kernel 6: deformable bilinear sampling ----------------
__global__ void sample_k(float* __restrict__ out) {
    int b  = blockIdx.x;
    int wt = b % (WW/16); b /= (WW/16);
    int h  = b % HH;      b /= HH;
    int g  = b % GG;
    int n  = b / GG;
    int w0 = wt * 16;
    int tid = threadIdx.x;

    __shared__ float oms[16][28];
    for (int t = tid; t < 16*27; t += 256) {
        int u = t / 27, j = t % 27;
        oms[u][j] = g_om[((size_t)(n*HWp + h*WW + w0 + u))*OMD + g*27 + j];
    }
    __syncthreads();

    int c = tid & 15;
    int u = tid >> 4;
    int wpix = w0 + u;
    const float* xb = g_xT + (size_t)n*CHW + g*GCg + c;

    float acc = 0.f;
    #pragma unroll
    for (int k = 0; k < 9; k++) {
        int ky = k / 3, kx = k % 3;
        float locy = (float)(h    + ky - 1) + oms[u][2*k + 1];
        float locx = (float)(wpix + kx - 1) + oms[u][2*k];
        float m    = oms[u][18 + k];
        float fy0 = floorf(locy), fx0 = floorf(locx);
        float ly = locy - fy0, lx = locx - fx0;
        int y0 = (int)fy0, x0 = (int)fx0;
        int y1 = y0 + 1,   x1 = x0 + 1;
        bool yo0 = (y0 >= 0) & (y0 < HH), yo1 = (y1 >= 0) & (y1 < HH);
        bool xo0 = (x0 >= 0) & (x0 < WW), xo1 = (x1 >= 0) & (x1 < WW);
        float v00 = (yo0 & xo0) ? xb[(size_t)(y0*WW + x0)*CC] : 0.f;
        float v01 = (yo0 & xo1) ? xb[(size_t)(y0*WW + x1)*CC] : 0.f;
        float v10 = (yo1 & xo0) ? xb[(size_t)(y1*WW + x0)*CC] : 0.f;
        float v11 = (yo1 & xo1) ? xb[(size_t)(y1*WW + x1)*CC] : 0.f;
        acc += m * (v00*(1.f-ly)*(1.f-lx) + v01*(1.f-ly)*lx
                  + v10*ly*(1.f-lx)       + v11*ly*lx);
    }

    __shared__ float tout[16][17];
    tout[c][u] = acc;
    __syncthreads();
    int c2 = tid >> 4, w2 = tid & 15;
    out[((size_t)(n*CC + g*GCg + c2))*HWp + h*WW + w0 + w2] = tout[c2][w2];
}

// ---------------- launch ----------------
extern "C" void kernel_launch(void* const* d_in, const int* in_sizes, int n_in,
                              void* d_out, int out_size) {
    const float* x    = (const float*)d_in[0];
    const float* dw_w = (const float*)d_in[1];
    const float* dw_b = (const float*)d_in[2];
    const float* gn_w = (const float*)d_in[3];
    const float* gn_b = (const float*)d_in[4];
    const float* om_w = (const float*)d_in[5];
    const float* om_b = (const float*)d_in[6];
    float* out = (float*)d_out;

    zero_stats_k<<<1, 32>>>();
    dwconv_k<<<NN*CC*HH*(WW/4)/256, 256>>>(x, dw_w, dw_b);
    finalize_k<<<1, 32>>>();

    dim3 tb(32, 8);
    dim3 tg(HWp/32, CC/32, NN);
    fused_transpose_k<<<tg, tb>>>(x, gn_w, gn_b);

    dim3 gg((NN*HWp)/GBM, OMD/GBN);   // 1152 x 3
    gemm_tf32_k<<<gg, 128>>>(om_w, om_b);

    sample_k<<<NN*GG*HH*(WW/16), 256>>>(out);
}

// round 10
// speedup vs baseline: 2.3990x; 1.3045x over previous
#include <cuda_runtime.h>
#include <math.h>

#define NN  8
#define CC  128
#define HH  96
#define WW  96
#define HWp (HH*WW)          // 9216
#define CHW (CC*HWp)         // 1179648
#define GG  8
#define GCg 16
#define OMD 216

// ---------------- scratch (device globals; no allocation) ----------------
__device__ float g_x1 [NN*CHW];        // dwconv output, NCHW
__device__ float g_act[NN*CHW];        // norm+gelu (tf32-rounded), NHWC (GEMM A)
__device__ float g_xT [NN*CHW];        // raw input transposed to NHWC
__device__ float g_om [(size_t)NN*HWp*OMD]; // linear head output
__device__ float g_sum[NN];
__device__ float g_sq [NN];
__device__ float g_mean[NN];
__device__ float g_rsig[NN];

__device__ __forceinline__ unsigned f2tf32(float x) {
    unsigned r;
    asm("cvt.rna.tf32.f32 %0, %1;" : "=r"(r) : "f"(x));
    return r;
}

// ---------------- kernel 0: zero stats (replay-safe) ----------------
__global__ void zero_stats_k() {
    int t = threadIdx.x;
    if (t < NN) { g_sum[t] = 0.f; g_sq[t] = 0.f; }
}

// ---------------- kernel 1: depthwise 3x3 conv + bias + partial stats ----------------
__global__ void dwconv_k(const float* __restrict__ x,
                         const float* __restrict__ dw_w,
                         const float* __restrict__ dw_b) {
    int idx = blockIdx.x * 256 + threadIdx.x;   // over NN*CC*HH*(WW/4)
    int wq = idx % (WW/4);
    int t  = idx / (WW/4);
    int h  = t % HH;  t /= HH;
    int c  = t % CC;
    int n  = t / CC;
    int w0 = wq * 4;

    const float* xp = x + ((size_t)n*CC + c)*HWp;
    const float* wp = dw_w + c*9;
    float bb = dw_b[c];
    float a0 = bb, a1 = bb, a2 = bb, a3 = bb;

    #pragma unroll
    for (int ky = 0; ky < 3; ky++) {
        int yy = h + ky - 1;
        if (yy < 0 || yy >= HH) continue;
        const float* row = xp + yy*WW + w0;
        float4 v  = *(const float4*)row;
        float vm  = (w0 > 0)       ? row[-1] : 0.f;
        float vp  = (w0 + 4 < WW)  ? row[4]  : 0.f;
        float k0 = wp[ky*3+0], k1 = wp[ky*3+1], k2 = wp[ky*3+2];
        a0 += k0*vm  + k1*v.x + k2*v.y;
        a1 += k0*v.x + k1*v.y + k2*v.z;
        a2 += k0*v.y + k1*v.z + k2*v.w;
        a3 += k0*v.z + k1*v.w + k2*vp;
    }
    *(float4*)&g_x1[((size_t)n*CC + c)*HWp + h*WW + w0] = make_float4(a0,a1,a2,a3);

    __shared__ float ssum[256];
    __shared__ float ssq [256];
    int tid = threadIdx.x;
    ssum[tid] = a0 + a1 + a2 + a3;
    ssq [tid] = a0*a0 + a1*a1 + a2*a2 + a3*a3;
    __syncthreads();
    for (int s = 128; s > 0; s >>= 1) {
        if (tid < s) { ssum[tid] += ssum[tid+s]; ssq[tid] += ssq[tid+s]; }
        __syncthreads();
    }
    if (tid == 0) {
        atomicAdd(&g_sum[n], ssum[0]);
        atomicAdd(&g_sq [n], ssq [0]);
    }
}

// ---------------- kernel 2: finalize mean / rsig ----------------
__global__ void finalize_k() {
    int t = threadIdx.x;
    if (t < NN) {
        float inv = 1.f / (float)CHW;
        float mu  = g_sum[t] * inv;
        float var = g_sq[t] * inv - mu*mu;
        g_mean[t] = mu;
        g_rsig[t] = rsqrtf(var + 1e-5f);
    }
}

// ---------------- kernel 3: fused (norm+GELU transpose, tf32-round) + (x transpose) ----------------
__global__ void fused_transpose_k(const float* __restrict__ x,
                                  const float* __restrict__ gn_w,
                                  const float* __restrict__ gn_b) {
    __shared__ float tA[32][33];
    __shared__ float tB[32][33];
    int n  = blockIdx.z;
    int c0 = blockIdx.y * 32;
    int p0 = blockIdx.x * 32;
    int tx = threadIdx.x, ty = threadIdx.y;  // 32 x 8

    const float* srcA = g_x1 + (size_t)n*CHW;
    const float* srcB = x    + (size_t)n*CHW;
    #pragma unroll
    for (int i = ty; i < 32; i += 8) {
        size_t off = (size_t)(c0 + i)*HWp + p0 + tx;
        tA[i][tx] = srcA[off];
        tB[i][tx] = srcB[off];
    }
    __syncthreads();

    float mu = g_mean[n], rs = g_rsig[n];
    int c = c0 + tx;
    float w = gn_w[c], b = gn_b[c];
    float* dstA = g_act + (size_t)n*CHW;
    float* dstB = g_xT  + (size_t)n*CHW;
    #pragma unroll
    for (int i = ty; i < 32; i += 8) {
        float y = (tA[tx][i] - mu) * rs * w + b;
        float g = 0.5f * y * (1.f + erff(y * 0.70710678118654752f));
        size_t off = (size_t)(p0 + i)*CC + c;
        dstA[off] = __uint_as_float(f2tf32(g));   // pre-rounded for mma
        dstB[off] = tB[tx][i];
    }
}

// ---------------- kernel 5: tf32 tensor-core GEMM  om = act @ om_w^T + om_b ----------------
#define GBM 64
#define GBN 72

__device__ __forceinline__ void mma_tf32(float* c,
                                         unsigned a0, unsigned a1, unsigned a2, unsigned a3,
                                         unsigned b0, unsigned b1) {
    asm volatile(
        "mma.sync.aligned.m16n8k8.row.col.f32.tf32.tf32.f32 "
        "{%0,%1,%2,%3}, {%4,%5,%6,%7}, {%8,%9}, {%0,%1,%2,%3};\n"
        : "+f"(c[0]), "+f"(c[1]), "+f"(c[2]), "+f"(c[3])
        : "r"(a0), "r"(a1), "r"(a2), "r"(a3), "r"(b0), "r"(b1));
}

__global__ void __launch_bounds__(128) gemm_tf32_k(const float* __restrict__ Bw,  // om_w [216,128]
                                                   const float* __restrict__ bias) {
    __shared__ float As[GBM][132];
    __shared__ float Bs[GBN][132];

    const int tid  = threadIdx.x;
    const int wid  = tid >> 5;
    const int lane = tid & 31;
    const int row0 = blockIdx.x * GBM;
    const int col0 = blockIdx.y * GBN;

    #pragma unroll
    for (int i = 0; i < 16; i++) {
        int idx = tid + i*128;
        int r  = idx >> 5;
        int kq = idx & 31;
        float4 v = *(const float4*)&g_act[(size_t)(row0 + r)*CC + kq*4];
        *(float4*)&As[r][kq*4] = v;
    }
    #pragma unroll
    for (int i = 0; i < 18; i++) {
        int idx = tid + i*128;
        int r  = idx >> 5;
        int kq = idx & 31;
        float4 v = *(const float4*)&Bw[(size_t)(col0 + r)*CC + kq*4];
        Bs[r][kq*4+0] = __uint_as_float(f2tf32(v.x));
        Bs[r][kq*4+1] = __uint_as_float(f2tf32(v.y));
        Bs[r][kq*4+2] = __uint_as_float(f2tf32(v.z));
        Bs[r][kq*4+3] = __uint_as_float(f2tf32(v.w));
    }
    __syncthreads();

    const int mrow = wid*16 + (lane >> 2);
    const int kl   = lane & 3;

    float acc[9][4];
    #pragma unroll
    for (int t = 0; t < 9; t++)
        acc[t][0] = acc[t][1] = acc[t][2] = acc[t][3] = 0.f;

    #pragma unroll
    for (int k0 = 0; k0 < 128; k0 += 8) {
        unsigned a0 = __float_as_uint(As[mrow    ][k0 + kl]);
        unsigned a1 = __float_as_uint(As[mrow + 8][k0 + kl]);
        unsigned a2 = __float_as_uint(As[mrow    ][k0 + 4 + kl]);
        unsigned a3 = __float_as_uint(As[mrow + 8][k0 + 4 + kl]);
        #pragma unroll
        for (int nt = 0; nt < 9; nt++) {
            int bcol = nt*8 + (lane >> 2);
            unsigned b0 = __float_as_uint(Bs[bcol][k0 + kl]);
            unsigned b1 = __float_as_uint(Bs[bcol][k0 + 4 + kl]);
            mma_tf32(acc[nt], a0, a1, a2, a3, b0, b1);
        }
    }

    const int rA = row0 + wid*16 + (lane >> 2);
    const int cBase = col0 + 2*(lane & 3);
    #pragma unroll
    for (int nt = 0; nt < 9; nt++) {
        int col = cBase + nt*8;
        float bx = bias[col], by = bias[col+1];
        *(float2*)&g_om[(size_t)rA*OMD + col]       = make_float2(acc[nt][0]+bx, acc[nt][1]+by);
        *(float2*)&g_om[(size_t)(rA+8)*OMD + col]   = make_float2(acc[nt][2]+bx, acc[nt][3]+by);
    }
}

// ---------------- kernel 6: deformable bilinear sampling (float4 channel quads) ----------------
// block: 128 threads = 32 pixels (u) x 4 channel-quads (cq); unit = (n,g,h,wtile32)
__global__ void sample_k(float* __restrict__ out) {
    int b  = blockIdx.x;
    int wt = b % (WW/32); b /= (WW/32);
    int h  = b % HH;      b /= HH;
    int g  = b % GG;
    int n  = b / GG;
    int w0 = wt * 32;
    int tid = threadIdx.x;

    __shared__ float oms[32][28];
    for (int t = tid; t < 32*27; t += 128) {
        int u = t / 27, j = t % 27;
        oms[u][j] = g_om[((size_t)(n*HWp + h*WW + w0 + u))*OMD + g*27 + j];
    }
    __syncthreads();

    int cq = tid & 3;    // channel quad 0..3
    int u  = tid >> 2;   // pixel 0..31
    int wpix = w0 + u;
    const float* xb = g_xT + (size_t)n*CHW + g*GCg + cq*4;

    float4 acc = make_float4(0.f, 0.f, 0.f, 0.f);
    #pragma unroll
    for (int k = 0; k < 9; k++) {
        int ky = k / 3, kx = k % 3;
        float locy = (float)(h    + ky - 1) + oms[u][2*k + 1];
        float locx = (float)(wpix + kx - 1) + oms[u][2*k];
        float m    = oms[u][18 + k];
        float fy0 = floorf(locy), fx0 = floorf(locx);
        float ly = locy - fy0, lx = locx - fx0;
        int y0 = (int)fy0, x0 = (int)fx0;
        int y1 = y0 + 1,   x1 = x0 + 1;
        bool yo0 = (y0 >= 0) & (y0 < HH), yo1 = (y1 >= 0) & (y1 < HH);
        bool xo0 = (x0 >= 0) & (x0 < WW), xo1 = (x1 >= 0) & (x1 < WW);
        float w00 = m * (1.f-ly) * (1.f-lx);
        float w01 = m * (1.f-ly) * lx;
        float w10 = m * ly * (1.f-lx);
        float w11 = m * ly * lx;
        float4 z = make_float4(0.f,0.f,0.f,0.f);
        float4 v00 = (yo0 & xo0) ? *(const float4*)&xb[(size_t)(y0*WW + x0)*CC] : z;
        float4 v01 = (yo0 & xo1) ? *(const float4*)&xb[(size_t)(y0*WW + x1)*CC] : z;
        float4 v10 = (yo1 & xo0) ? *(const float4*)&xb[(size_t)(y1*WW + x0)*CC] : z;
        float4 v11 = (yo1 & xo1) ? *(const float4*)&xb[(size_t)(y1*WW + x1)*CC] : z;
        acc.x += w00*v00.x + w01*v01.x + w10*v10.x + w11*v11.x;
        acc.y += w00*v00.y + w01*v01.y + w10*v10.y + w11*v11.y;
        acc.z += w00*v00.z + w01*v01.z + w10*v10.z + w11*v11.z;
        acc.w += w00*v00.w + w01*v01.w + w10*v10.w + w11*v11.w;
    }

    // stage for coalesced NCHW stores: [16 ch][32 w]
    __shared__ float tout[16][33];
    tout[cq*4+0][u] = acc.x;
    tout[cq*4+1][u] = acc.y;
    tout[cq*4+2][u] = acc.z;
    tout[cq*4+3][u] = acc.w;
    __syncthreads();

    // 128 threads write 512 floats: thread -> (c, 4 consecutive w)
    int c2 = tid >> 3;          // 0..15
    int ws = (tid & 7) * 4;     // 0,4,...,28
    float4 vv = make_float4(tout[c2][ws], tout[c2][ws+1], tout[c2][ws+2], tout[c2][ws+3]);
    *(float4*)&out[((size_t)(n*CC + g*GCg + c2))*HWp + h*WW + w0 + ws] = vv;
}

// ---------------- launch ----------------
extern "C" void kernel_launch(void* const* d_in, const int* in_sizes, int n_in,
                              void* d_out, int out_size) {
    const float* x    = (const float*)d_in[0];
    const float* dw_w = (const float*)d_in[1];
    const float* dw_b = (const float*)d_in[2];
    const float* gn_w = (const float*)d_in[3];
    const float* gn_b = (const float*)d_in[4];
    const float* om_w = (const float*)d_in[5];
    const float* om_b = (const float*)d_in[6];
    float* out = (float*)d_out;

    zero_stats_k<<<1, 32>>>();
    dwconv_k<<<NN*CC*HH*(WW/4)/256, 256>>>(x, dw_w, dw_b);
    finalize_k<<<1, 32>>>();

    dim3 tb(32, 8);
    dim3 tg(HWp/32, CC/32, NN);
    fused_transpose_k<<<tg, tb>>>(x, gn_w, gn_b);

    dim3 gg((NN*HWp)/GBM, OMD/GBN);   // 1152 x 3
    gemm_tf32_k<<<gg, 128>>>(om_w, om_b);

    sample_k<<<NN*GG*HH*(WW/32), 128>>>(out);
}

// round 13
// speedup vs baseline: 2.5519x; 1.0638x over previous
#include <cuda_runtime.h>
#include <math.h>

#define NN  8
#define CC  128
#define HH  96
#define WW  96
#define HWp (HH*WW)          // 9216
#define CHW (CC*HWp)         // 1179648
#define GG  8
#define GCg 16
#define OMD 216

// ---------------- scratch (device globals; no allocation) ----------------
__device__ float g_x1 [NN*CHW];        // dwconv output, NCHW
__device__ float g_act[NN*CHW];        // norm+gelu (tf32-rounded), NHWC (GEMM A)
__device__ float g_xT [NN*CHW];        // raw input transposed to NHWC
__device__ float g_om [(size_t)NN*HWp*OMD]; // linear head output
__device__ float g_sum[NN];
__device__ float g_sq [NN];
__device__ float g_mean[NN];
__device__ float g_rsig[NN];

__device__ __forceinline__ unsigned f2tf32(float x) {
    unsigned r;
    asm("cvt.rna.tf32.f32 %0, %1;" : "=r"(r) : "f"(x));
    return r;
}

// ---------------- kernel 0: zero stats (replay-safe) ----------------
__global__ void zero_stats_k() {
    int t = threadIdx.x;
    if (t < NN) { g_sum[t] = 0.f; g_sq[t] = 0.f; }
}

// ---------------- kernel 1: depthwise 3x3 conv + bias + partial stats ----------------
__global__ void dwconv_k(const float* __restrict__ x,
                         const float* __restrict__ dw_w,
                         const float* __restrict__ dw_b) {
    int idx = blockIdx.x * 256 + threadIdx.x;   // over NN*CC*HH*(WW/4)
    int wq = idx % (WW/4);
    int t  = idx / (WW/4);
    int h  = t % HH;  t /= HH;
    int c  = t % CC;
    int n  = t / CC;
    int w0 = wq * 4;

    const float* xp = x + ((size_t)n*CC + c)*HWp;
    const float* wp = dw_w + c*9;
    float bb = dw_b[c];
    float a0 = bb, a1 = bb, a2 = bb, a3 = bb;

    #pragma unroll
    for (int ky = 0; ky < 3; ky++) {
        int yy = h + ky - 1;
        if (yy < 0 || yy >= HH) continue;
        const float* row = xp + yy*WW + w0;
        float4 v  = *(const float4*)row;
        float vm  = (w0 > 0)       ? row[-1] : 0.f;
        float vp  = (w0 + 4 < WW)  ? row[4]  : 0.f;
        float k0 = wp[ky*3+0], k1 = wp[ky*3+1], k2 = wp[ky*3+2];
        a0 += k0*vm  + k1*v.x + k2*v.y;
        a1 += k0*v.x + k1*v.y + k2*v.z;
        a2 += k0*v.y + k1*v.z + k2*v.w;
        a3 += k0*v.z + k1*v.w + k2*vp;
    }
    *(float4*)&g_x1[((size_t)n*CC + c)*HWp + h*WW + w0] = make_float4(a0,a1,a2,a3);

    __shared__ float ssum[256];
    __shared__ float ssq [256];
    int tid = threadIdx.x;
    ssum[tid] = a0 + a1 + a2 + a3;
    ssq [tid] = a0*a0 + a1*a1 + a2*a2 + a3*a3;
    __syncthreads();
    for (int s = 128; s > 0; s >>= 1) {
        if (tid < s) { ssum[tid] += ssum[tid+s]; ssq[tid] += ssq[tid+s]; }
        __syncthreads();
    }
    if (tid == 0) {
        atomicAdd(&g_sum[n], ssum[0]);
        atomicAdd(&g_sq [n], ssq [0]);
    }
}

// ---------------- kernel 2: finalize mean / rsig ----------------
__global__ void finalize_k() {
    int t = threadIdx.x;
    if (t < NN) {
        float inv = 1.f / (float)CHW;
        float mu  = g_sum[t] * inv;
        float var = g_sq[t] * inv - mu*mu;
        g_mean[t] = mu;
        g_rsig[t] = rsqrtf(var + 1e-5f);
    }
}

// ---------------- kernel 3: fused transposes, vectorized stores ----------------
__global__ void __launch_bounds__(256) fused_transpose_k(const float* __restrict__ x,
                                                         const float* __restrict__ gn_w,
                                                         const float* __restrict__ gn_b) {
    __shared__ float tA[32][33];
    __shared__ float tB[32][33];
    int n  = blockIdx.z;
    int c0 = blockIdx.y * 32;
    int p0 = blockIdx.x * 32;
    int tid = threadIdx.x;
    int tx = tid & 31, ty = tid >> 5;   // 32 x 8

    const float* srcA = g_x1 + (size_t)n*CHW;
    const float* srcB = x    + (size_t)n*CHW;
    #pragma unroll
    for (int i = ty; i < 32; i += 8) {
        size_t off = (size_t)(c0 + i)*HWp + p0 + tx;
        tA[i][tx] = srcA[off];
        tB[i][tx] = srcB[off];
    }
    __syncthreads();

    // store phase: thread -> (p = tid>>3, 4 consecutive c = (tid&7)*4)
    int p  = tid >> 3;
    int c4 = tid & 7;
    int cbase = c0 + c4*4;
    float mu = g_mean[n], rs = g_rsig[n];
    float4 wv = *(const float4*)&gn_w[cbase];
    float4 bv = *(const float4*)&gn_b[cbase];
    float wa[4] = {wv.x, wv.y, wv.z, wv.w};
    float ba[4] = {bv.x, bv.y, bv.z, bv.w};

    float4 go, xo;
    float* gp = &go.x;
    float* xp2 = &xo.x;
    #pragma unroll
    for (int j = 0; j < 4; j++) {
        float y = (tA[c4*4 + j][p] - mu) * rs * wa[j] + ba[j];
        float g = 0.5f * y * (1.f + erff(y * 0.70710678118654752f));
        gp[j]  = __uint_as_float(f2tf32(g));
        xp2[j] = tB[c4*4 + j][p];
    }
    size_t off = (size_t)(p0 + p)*CC + cbase;
    *(float4*)&g_act[(size_t)n*CHW + off] = go;
    *(float4*)&g_xT [(size_t)n*CHW + off] = xo;
}

// ---------------- kernel 5: tf32 tensor-core GEMM  om = act @ om_w^T + om_b ----------------
#define GBM 64
#define GBN 72

__device__ __forceinline__ void mma_tf32(float* c,
                                         unsigned a0, unsigned a1, unsigned a2, unsigned a3,
                                         unsigned b0, unsigned b1) {
    asm volatile(
        "mma.sync.aligned.m16n8k8.row.col.f32.tf32.tf32.f32 "
        "{%0,%1,%2,%3}, {%4,%5,%6,%7}, {%8,%9}, {%0,%1,%2,%3};\n"
        : "+f"(c[0]), "+f"(c[1]), "+f"(c[2]), "+f"(c[3])
        : "r"(a0), "r"(a1), "r"(a2), "r"(a3), "r"(b0), "r"(b1));
}

__global__ void __launch_bounds__(128) gemm_tf32_k(const float* __restrict__ Bw,  // om_w [216,128]
                                                   const float* __restrict__ bias) {
    __shared__ float As[GBM][132];
    __shared__ float Bs[GBN][132];

    const int tid  = threadIdx.x;
    const int wid  = tid >> 5;
    const int lane = tid & 31;
    const int row0 = blockIdx.x * GBM;
    const int col0 = blockIdx.y * GBN;

    #pragma unroll
    for (int i = 0; i < 16; i++) {
        int idx = tid + i*128;
        int r  = idx >> 5;
        int kq = idx & 31;
        float4 v = *(const float4*)&g_act[(size_t)(row0 + r)*CC + kq*4];
        *(float4*)&As[r][kq*4] = v;
    }
    #pragma unroll
    for (int i = 0; i < 18; i++) {
        int idx = tid + i*128;
        int r  = idx >> 5;
        int kq = idx & 31;
        float4 v = *(const float4*)&Bw[(size_t)(col0 + r)*CC + kq*4];
        Bs[r][kq*4+0] = __uint_as_float(f2tf32(v.x));
        Bs[r][kq*4+1] = __uint_as_float(f2tf32(v.y));
        Bs[r][kq*4+2] = __uint_as_float(f2tf32(v.z));
        Bs[r][kq*4+3] = __uint_as_float(f2tf32(v.w));
    }
    __syncthreads();

    const int mrow = wid*16 + (lane >> 2);
    const int kl   = lane & 3;

    float acc[9][4];
    #pragma unroll
    for (int t = 0; t < 9; t++)
        acc[t][0] = acc[t][1] = acc[t][2] = acc[t][3] = 0.f;

    #pragma unroll
    for (int k0 = 0; k0 < 128; k0 += 8) {
        unsigned a0 = __float_as_uint(As[mrow    ][k0 + kl]);
        unsigned a1 = __float_as_uint(As[mrow + 8][k0 + kl]);
        unsigned a2 = __float_as_uint(As[mrow    ][k0 + 4 + kl]);
        unsigned a3 = __float_as_uint(As[mrow + 8][k0 + 4 + kl]);
        #pragma unroll
        for (int nt = 0; nt < 9; nt++) {
            int bcol = nt*8 + (lane >> 2);
            unsigned b0 = __float_as_uint(Bs[bcol][k0 + kl]);
            unsigned b1 = __float_as_uint(Bs[bcol][k0 + 4 + kl]);
            mma_tf32(acc[nt], a0, a1, a2, a3, b0, b1);
        }
    }

    const int rA = row0 + wid*16 + (lane >> 2);
    const int cBase = col0 + 2*(lane & 3);
    #pragma unroll
    for (int nt = 0; nt < 9; nt++) {
        int col = cBase + nt*8;
        float bx = bias[col], by = bias[col+1];
        *(float2*)&g_om[(size_t)rA*OMD + col]       = make_float2(acc[nt][0]+bx, acc[nt][1]+by);
        *(float2*)&g_om[(size_t)(rA+8)*OMD + col]   = make_float2(acc[nt][2]+bx, acc[nt][3]+by);
    }
}

// ---------------- kernel 6: deformable bilinear sampling, smem-windowed ----------------
// block: 128 threads = 32 pixels (u) x 4 channel-quads (cq); unit = (n,g,h,wtile32)
// x window [h-2,h+2] x [w0-2,w0+33] staged in smem (out-of-image = 0), global fallback.
#define WIN_X 36
#define WIN_C (5*WIN_X)      // 180 cells

__global__ void __launch_bounds__(128) sample_k(float* __restrict__ out) {
    int b  = blockIdx.x;
    int wt = b % (WW/32); b /= (WW/32);
    int h  = b % HH;      b /= HH;
    int g  = b % GG;
    int n  = b / GG;
    int w0 = wt * 32;
    int tid = threadIdx.x;

    __shared__ float  oms[32][28];
    __shared__ float4 ss4[WIN_C*4];    // [cell][cq], cell = yy*36+xx
    __shared__ float  tout[16][33];

    for (int t = tid; t < 32*27; t += 128) {
        int u = t / 27, j = t % 27;
        oms[u][j] = g_om[((size_t)(n*HWp + h*WW + w0 + u))*OMD + g*27 + j];
    }

    const float* xg = g_xT + (size_t)n*CHW + g*GCg;
    for (int t = tid; t < WIN_C*4; t += 128) {
        int cq2  = t & 3;
        int cell = t >> 2;
        int xx = cell % WIN_X;
        int yy = cell / WIN_X;
        int gy = h - 2 + yy;
        int gx = w0 - 2 + xx;
        float4 v = make_float4(0.f,0.f,0.f,0.f);
        if (gy >= 0 && gy < HH && gx >= 0 && gx < WW)
            v = *(const float4*)&xg[(size_t)(gy*WW + gx)*CC + cq2*4];
        ss4[cell*4 + cq2] = v;
    }
    __syncthreads();

    int cq = tid & 3;
    int u  = tid >> 2;
    int wpix = w0 + u;
    const float* xb = xg + cq*4;

    float4 acc = make_float4(0.f, 0.f, 0.f, 0.f);
    #pragma unroll
    for (int k = 0; k < 9; k++) {
        int ky = k / 3, kx = k % 3;
        float locy = (float)(h    + ky - 1) + oms[u][2*k + 1];
        float locx = (float)(wpix + kx - 1) + oms[u][2*k];
        float m    = oms[u][18 + k];
        float fy0 = floorf(locy), fx0 = floorf(locx);
        float ly = locy - fy0, lx = locx - fx0;
        int y0 = (int)fy0, x0 = (int)fx0;
        float w00 = m * (1.f-ly) * (1.f-lx);
        float w01 = m * (1.f-ly) * lx;
        float w10 = m * ly * (1.f-lx);
        float w11 = m * ly * lx;

        int y0l = y0 - (h - 2);
        int x0l = x0 - (w0 - 2);
        float4 v00, v01, v10, v11;
        if ((unsigned)y0l <= 3u && (unsigned)x0l <= 34u) {
            // fast path: window smem (zeros already encode out-of-image)
            const float4* base = &ss4[(y0l*WIN_X + x0l)*4 + cq];
            v00 = base[0];
            v01 = base[4];
            v10 = base[WIN_X*4];
            v11 = base[WIN_X*4 + 4];
        } else {
            // slow path: global with masks (numerically identical)
            int y1 = y0 + 1, x1 = x0 + 1;
            bool yo0 = (y0 >= 0) & (y0 < HH), yo1 = (y1 >= 0) & (y1 < HH);
            bool xo0 = (x0 >= 0) & (x0 < WW), xo1 = (x1 >= 0) & (x1 < WW);
            float4 z = make_float4(0.f,0.f,0.f,0.f);
            v00 = (yo0 & xo0) ? *(const float4*)&xb[(size_t)(y0*WW + x0)*CC] : z;
            v01 = (yo0 & xo1) ? *(const float4*)&xb[(size_t)(y0*WW + x1)*CC] : z;
            v10 = (yo1 & xo0) ? *(const float4*)&xb[(size_t)(y1*WW + x0)*CC] : z;
            v11 = (yo1 & xo1) ? *(const float4*)&xb[(size_t)(y1*WW + x1)*CC] : z;
        }
        acc.x += w00*v00.x + w01*v01.x + w10*v10.x + w11*v11.x;
        acc.y += w00*v00.y + w01*v01.y + w10*v10.y + w11*v11.y;
        acc.z += w00*v00.z + w01*v01.z + w10*v10.z + w11*v11.z;
        acc.w += w00*v00.w + w01*v01.w + w10*v10.w + w11*v11.w;
    }

    tout[cq*4+0][u] = acc.x;
    tout[cq*4+1][u] = acc.y;
    tout[cq*4+2][u] = acc.z;
    tout[cq*4+3][u] = acc.w;
    __syncthreads();

    int c2 = tid >> 3;
    int ws = (tid & 7) * 4;
    float4 vv = make_float4(tout[c2][ws], tout[c2][ws+1], tout[c2][ws+2], tout[c2][ws+3]);
    *(float4*)&out[((size_t)(n*CC + g*GCg + c2))*HWp + h*WW + w0 + ws] = vv;
}

// ---------------- launch ----------------
extern "C" void kernel_launch(void* const* d_in, const int* in_sizes, int n_in,
                              void* d_out, int out_size) {
    const float* x    = (const float*)d_in[0];
    const float* dw_w = (const float*)d_in[1];
    const float* dw_b = (const float*)d_in[2];
    const float* gn_w = (const float*)d_in[3];
    const float* gn_b = (const float*)d_in[4];
    const float* om_w = (const float*)d_in[5];
    const float* om_b = (const float*)d_in[6];
    float* out = (float*)d_out;

    zero_stats_k<<<1, 32>>>();
    dwconv_k<<<NN*CC*HH*(WW/4)/256, 256>>>(x, dw_w, dw_b);
    finalize_k<<<1, 32>>>();

    dim3 tg(HWp/32, CC/32, NN);
    fused_transpose_k<<<tg, 256>>>(x, gn_w, gn_b);

    dim3 gg((NN*HWp)/GBM, OMD/GBN);   // 1152 x 3
    gemm_tf32_k<<<gg, 128>>>(om_w, om_b);

    sample_k<<<NN*GG*HH*(WW/32), 128>>>(out);
}